// round 14
// baseline (speedup 1.0000x reference)
#include <cuda_runtime.h>
#include <cuda_bf16.h>
#include <cstdint>
#include <cstddef>
#include <math.h>

// ---------------- problem constants ----------------
#define Bimg 64
#define Hdim 56
#define Wdim 56
#define WS 7
#define SHIFT 3
#define Cdim 128
#define NHn 4
#define HDd 32
#define Nn 49
#define NWn 64
#define HID 512
#define SCALE 0.17677669529663688f

#define NWIN_TOTAL (Bimg * NWn)          // 4096
#define NWIN_HALF  (NWIN_TOTAL / 2)      // 2048
#define TOK_TOTAL  (NWIN_TOTAL * Nn)     // 200704
#define TOK_HALF   (NWIN_HALF * Nn)      // 100352
#define MCH        50176                 // MLP M-chunk (L2-resident H)

typedef __nv_bfloat16 bf16;
typedef __nv_bfloat162 bf162;

// ---------------- scratch (device globals) ----------------
__device__ bf16  g_XW  [(size_t)TOK_TOTAL * Cdim];
__device__ bf16  g_QKVf[(size_t)TOK_TOTAL * 384];
__device__ bf16  g_QKV1[(size_t)TOK_HALF  * 384];
__device__ bf16  g_QKV2[(size_t)TOK_HALF  * 384];
__device__ bf16  g_O   [(size_t)TOK_TOTAL * Cdim];
__device__ bf16  g_Oh1 [(size_t)TOK_HALF  * Cdim];
__device__ bf16  g_Oh2 [(size_t)TOK_HALF  * Cdim];
__device__ bf16  g_XN  [(size_t)TOK_TOTAL * Cdim];
__device__ bf16  g_H   [(size_t)MCH * HID];
__device__ bf16  g_H1  [(size_t)MCH * HID];
__device__ bf16  g_H2  [(size_t)MCH * HID];
__device__ float g_CB  [(size_t)NWn * NHn * Nn * Nn];
__device__ bf16  g_Wb  [196608];   // bf16 weights: qkvw|projw|f1w|f2w

// ---------------- fused prep: weights->bf16, bias+mask, LN1+roll+partition ----------------
#define PREP_W 192
#define PREP_B 256
#define PREP_LN (TOK_TOTAL / 8)
__global__ __launch_bounds__(256) void prep_kernel(
    const float* __restrict__ qkvw, const float* __restrict__ projw,
    const float* __restrict__ f1w, const float* __restrict__ f2w,
    bf16* __restrict__ Wb,
    const float* __restrict__ rbt, const int* __restrict__ relIdx,
    const float* __restrict__ mask, float* __restrict__ CB,
    const float* __restrict__ x, const float* __restrict__ n1w,
    const float* __restrict__ n1b, bf16* __restrict__ XW) {
    int bid = blockIdx.x;
    if (bid < PREP_W) {
        int i = (bid * 256 + threadIdx.x) * 4;
        const float* src; int off;
        if (i < 49152)       { src = qkvw;  off = i; }
        else if (i < 65536)  { src = projw; off = i - 49152; }
        else if (i < 131072) { src = f1w;   off = i - 65536; }
        else                 { src = f2w;   off = i - 131072; }
        float4 v = *(const float4*)(src + off);
        *(bf162*)(Wb + i)     = __floats2bfloat162_rn(v.x, v.y);
        *(bf162*)(Wb + i + 2) = __floats2bfloat162_rn(v.z, v.w);
        return;
    }
    if (bid < PREP_W + PREP_B) {
        int b = bid - PREP_W;
        int mi = b >> 2, h = b & 3;
        float* dst = CB + ((size_t)mi * NHn + h) * (Nn * Nn);
        const float* msk = mask + (size_t)mi * (Nn * Nn);
        for (int idx = threadIdx.x; idx < Nn * Nn; idx += 256)
            dst[idx] = __ldg(&rbt[relIdx[idx] * NHn + h]) + msk[idx];
        return;
    }
    int t = (bid - PREP_W - PREP_B) * 8 + (threadIdx.x >> 5);
    int lane = threadIdx.x & 31;
    int win = t / Nn, n = t - win * Nn;
    int bi = win >> 6, wi = win & 63;
    int hs = ((wi >> 3) * WS + n / WS + SHIFT) % Hdim;
    int ws = ((wi & 7) * WS + n % WS + SHIFT) % Wdim;
    const float* xp = x + ((size_t)bi * (Hdim * Wdim) + hs * Wdim + ws) * Cdim;
    float4 v = *(const float4*)(xp + lane * 4);
    float s  = v.x + v.y + v.z + v.w;
    float s2 = v.x * v.x + v.y * v.y + v.z * v.z + v.w * v.w;
    #pragma unroll
    for (int o = 16; o > 0; o >>= 1) {
        s  += __shfl_xor_sync(0xffffffffu, s, o);
        s2 += __shfl_xor_sync(0xffffffffu, s2, o);
    }
    float mu  = s * (1.0f / Cdim);
    float var = s2 * (1.0f / Cdim) - mu * mu;
    float inv = rsqrtf(var + 1e-5f);
    float4 wv = *(const float4*)(n1w + lane * 4);
    float4 bv = *(const float4*)(n1b + lane * 4);
    bf16* dst = XW + (size_t)t * Cdim + lane * 4;
    *(bf162*)(dst)     = __floats2bfloat162_rn((v.x - mu) * inv * wv.x + bv.x,
                                               (v.y - mu) * inv * wv.y + bv.y);
    *(bf162*)(dst + 2) = __floats2bfloat162_rn((v.z - mu) * inv * wv.z + bv.z,
                                               (v.w - mu) * inv * wv.w + bv.w);
}

// ---------------- LN2 (image layout, out holds residual already) ----------------
__global__ __launch_bounds__(256) void ln2_kernel(const float* __restrict__ out,
                                                  const float* __restrict__ w,
                                                  const float* __restrict__ b,
                                                  bf16* __restrict__ XN) {
    int t = blockIdx.x * 8 + (threadIdx.x >> 5);
    int lane = threadIdx.x & 31;
    float4 v = *(const float4*)(out + (size_t)t * Cdim + lane * 4);
    float s  = v.x + v.y + v.z + v.w;
    float s2 = v.x * v.x + v.y * v.y + v.z * v.z + v.w * v.w;
    #pragma unroll
    for (int o = 16; o > 0; o >>= 1) {
        s  += __shfl_xor_sync(0xffffffffu, s, o);
        s2 += __shfl_xor_sync(0xffffffffu, s2, o);
    }
    float mu  = s * (1.0f / Cdim);
    float var = s2 * (1.0f / Cdim) - mu * mu;
    float inv = rsqrtf(var + 1e-5f);
    float4 wv = *(const float4*)(w + lane * 4);
    float4 bv = *(const float4*)(b + lane * 4);
    bf16* dst = XN + (size_t)t * Cdim + lane * 4;
    *(bf162*)(dst)     = __floats2bfloat162_rn((v.x - mu) * inv * wv.x + bv.x,
                                               (v.y - mu) * inv * wv.y + bv.y);
    *(bf162*)(dst + 2) = __floats2bfloat162_rn((v.z - mu) * inv * wv.z + bv.z,
                                               (v.w - mu) * inv * wv.w + bv.w);
}

// ---------------- mma / ldmatrix helpers ----------------
__device__ __forceinline__ void mma_bf16(float* c, const uint32_t* a, uint32_t b0, uint32_t b1) {
    asm volatile("mma.sync.aligned.m16n8k16.row.col.f32.bf16.bf16.f32 "
        "{%0,%1,%2,%3}, {%4,%5,%6,%7}, {%8,%9}, {%0,%1,%2,%3};\n"
        : "+f"(c[0]), "+f"(c[1]), "+f"(c[2]), "+f"(c[3])
        : "r"(a[0]), "r"(a[1]), "r"(a[2]), "r"(a[3]), "r"(b0), "r"(b1));
}
__device__ __forceinline__ void ldsm_x4(uint32_t* r, const bf16* p) {
    uint32_t addr = (uint32_t)__cvta_generic_to_shared(p);
    asm volatile("ldmatrix.sync.aligned.m8n8.x4.shared.b16 {%0,%1,%2,%3}, [%4];\n"
        : "=r"(r[0]), "=r"(r[1]), "=r"(r[2]), "=r"(r[3]) : "r"(addr));
}
__device__ __forceinline__ void cpa16(uint32_t dst, const void* src, bool pred) {
    int sz = pred ? 16 : 0;
    asm volatile("cp.async.cg.shared.global [%0], [%1], 16, %2;\n"
                 :: "r"(dst), "l"(src), "r"(sz));
}
__device__ __forceinline__ uint32_t packbf(float a, float b) {
    bf162 t = __floats2bfloat162_rn(a, b);
    return *(uint32_t*)&t;
}
__device__ __forceinline__ float gelu_f(float v) {
    return 0.5f * v * (1.0f + erff(v * 0.70710678118654752f));
}
__device__ __forceinline__ size_t perm_pos(int r) {
    int win = r / Nn, n = r - win * Nn;
    int bi = win >> 6, wi = win & 63;
    int hs = ((wi >> 3) * WS + n / WS + SHIFT) % Hdim;
    int ws = ((wi & 7) * WS + n % WS + SHIFT) % Wdim;
    return ((size_t)bi * (Hdim * Wdim) + hs * Wdim + ws) * Cdim;
}

// ---------------- persistent BF16 GEMM ----------------
// outMode: 0 = bf16 store (ldc), 1 = perm + x add (fp32), 2 = perm RMW (fp32),
//          3 = linear fp32 RMW (C preoffset, ldc)
#define BM 128
#define BN 128
#define BK 32
#define GST 40
#define STG_E (BM * GST)
#define NSTG 4
#define GEMM_SMEM (NSTG * 2 * STG_E * 2)

__global__ __launch_bounds__(256, 2) void bgemm(
    const bf16* __restrict__ A, int lda,
    const bf16* __restrict__ B, int ldb,
    const float* __restrict__ bias,
    void* __restrict__ Cv, int ldc,
    int M, int N, int K,
    const float* __restrict__ gwPtr, int alphaIdx, int alphaMode, int splitM,
    int doGelu, int outMode,
    bf16* __restrict__ pfx2, bf16* __restrict__ pfx1, int pfxLd,
    const float* __restrict__ xres, int rowOffset) {
    extern __shared__ bf16 smem[];
    bf16* As = smem;
    bf16* Bs = smem + NSTG * STG_E;

    const int tid = threadIdx.x;
    const int bn = blockIdx.x * BN;
    const int wid = tid >> 5, lane = tid & 31;
    const int wm = (wid & 3) * 32;
    const int wn = (wid >> 2) * 64;
    const int g4 = lane >> 2, t4 = lane & 3;

    const int lrow = tid >> 2;
    const int lc = (tid & 3) * 8;
    const bf16* Bg = B + (size_t)(bn + lrow) * ldb + lc;
    const bool bval0 = (bn + lrow) < N;
    const bool bval1 = (bn + lrow + 64) < N;

    const int KI = K / BK;
    const int kiLog = (KI == 16) ? 4 : 2;
    const int kiMask = KI - 1;
    const bool resB = (KI == 4);
    const int nT = M / BM;
    const int GYm = gridDim.y;
    const int myT = (nT - (int)blockIdx.y + GYm - 1) / GYm;
    if (myT <= 0) return;
    const int G = myT * KI;

    float acc[2][8][4];
    auto tileBM = [&](int t) { return ((int)blockIdx.y + t * GYm) * BM; };

    auto issue = [&](int g) {
        int t = g >> kiLog, k = g & kiMask;
        int bm = tileBM(t);
        int st = g & 3;
        uint32_t a0 = (uint32_t)__cvta_generic_to_shared(&As[st * STG_E + lrow * GST + lc]);
        const bf16* Agp = A + (size_t)(bm + lrow) * lda + k * BK + lc;
        cpa16(a0, Agp, true);
        cpa16(a0 + 64 * GST * 2, Agp + (size_t)64 * lda, true);
        if (!resB || g < 4) {
            uint32_t b0 = (uint32_t)__cvta_generic_to_shared(&Bs[st * STG_E + lrow * GST + lc]);
            cpa16(b0, Bg + k * BK, bval0);
            cpa16(b0 + 64 * GST * 2, Bg + k * BK + (size_t)64 * ldb, bval1);
        }
        asm volatile("cp.async.commit_group;\n");
    };

    auto computeStage = [&](int st) {
        const bf16* Ab = &As[st * STG_E];
        const bf16* Bb = &Bs[st * STG_E];
        #pragma unroll
        for (int ks = 0; ks < 2; ks++) {
            const int kb = ks * 16;
            uint32_t af[2][4];
            #pragma unroll
            for (int mt = 0; mt < 2; mt++)
                ldsm_x4(af[mt], &Ab[(wm + mt * 16 + (lane & 15)) * GST + kb + ((lane >> 4) << 3)]);
            uint32_t bfm[8][2];
            #pragma unroll
            for (int nt2 = 0; nt2 < 4; nt2++) {
                uint32_t r4[4];
                ldsm_x4(r4, &Bb[(wn + nt2 * 16 + (lane & 7) + ((lane >> 4) << 3)) * GST
                                 + kb + (((lane >> 3) & 1) << 3)]);
                bfm[nt2 * 2][0] = r4[0]; bfm[nt2 * 2][1] = r4[1];
                bfm[nt2 * 2 + 1][0] = r4[2]; bfm[nt2 * 2 + 1][1] = r4[3];
            }
            #pragma unroll
            for (int nt = 0; nt < 8; nt++) {
                mma_bf16(acc[0][nt], af[0], bfm[nt][0], bfm[nt][1]);
                mma_bf16(acc[1][nt], af[1], bfm[nt][0], bfm[nt][1]);
            }
        }
    };

    auto snapshot = [&](bf16* __restrict__ P, int bm) {
        #pragma unroll
        for (int nt = 0; nt < 8; nt++) {
            int c0 = bn + wn + nt * 8 + t4 * 2;
            if (c0 >= N) continue;
            float bv0 = bias ? bias[c0] : 0.0f;
            float bv1 = bias ? bias[c0 + 1] : 0.0f;
            #pragma unroll
            for (int mt = 0; mt < 2; mt++)
                #pragma unroll
                for (int half = 0; half < 2; half++) {
                    int r = bm + wm + mt * 16 + g4 + half * 8;
                    float v0 = acc[mt][nt][half * 2 + 0] + bv0;
                    float v1 = acc[mt][nt][half * 2 + 1] + bv1;
                    if (doGelu) { v0 = gelu_f(v0); v1 = gelu_f(v1); }
                    *(bf162*)(P + (size_t)(r - splitM) * pfxLd + c0)
                        = __floats2bfloat162_rn(v0, v1);
                }
        }
    };

    auto epilogue = [&](int bm) {
        float alpha = 1.0f;
        if (alphaMode == 1) alpha = __ldg(&gwPtr[alphaIdx]);
        else if (alphaMode == 2 && bm >= splitM) alpha = __ldg(&gwPtr[0]);
        size_t pos[2][2];
        if (outMode == 1 || outMode == 2) {
            #pragma unroll
            for (int mt = 0; mt < 2; mt++)
                #pragma unroll
                for (int half = 0; half < 2; half++)
                    pos[mt][half] = perm_pos(rowOffset + bm + wm + mt * 16 + g4 + half * 8);
        }
        #pragma unroll
        for (int nt = 0; nt < 8; nt++) {
            int c0 = bn + wn + nt * 8 + t4 * 2;
            if (c0 >= N) continue;
            float bv0 = bias ? bias[c0] : 0.0f;
            float bv1 = bias ? bias[c0 + 1] : 0.0f;
            #pragma unroll
            for (int mt = 0; mt < 2; mt++) {
                #pragma unroll
                for (int half = 0; half < 2; half++) {
                    int r = bm + wm + mt * 16 + g4 + half * 8;
                    float v0 = acc[mt][nt][half * 2 + 0] + bv0;
                    float v1 = acc[mt][nt][half * 2 + 1] + bv1;
                    if (doGelu) { v0 = gelu_f(v0); v1 = gelu_f(v1); }
                    v0 *= alpha; v1 *= alpha;
                    if (outMode == 0) {
                        size_t off = (size_t)r * ldc + c0;
                        *(bf162*)((bf16*)Cv + off) = __floats2bfloat162_rn(v0, v1);
                    } else if (outMode == 3) {
                        float* Cf = (float*)Cv;
                        size_t off = (size_t)r * ldc + c0;
                        float2 old = *(const float2*)(Cf + off);
                        *(float2*)(Cf + off) = make_float2(old.x + v0, old.y + v1);
                    } else {
                        size_t off = pos[mt][half] + c0;
                        float* Cf = (float*)Cv;
                        if (outMode == 1) {
                            float2 xv = *(const float2*)(xres + off);
                            v0 += xv.x; v1 += xv.y;
                        } else {
                            float2 old = *(const float2*)(Cf + off);
                            v0 += old.x; v1 += old.y;
                        }
                        *(float2*)(Cf + off) = make_float2(v0, v1);
                    }
                }
            }
        }
    };

    issue(0); issue(1); issue(2);

    #pragma unroll 1
    for (int g = 0; g < G; g++) {
        int rem = G - 1 - g;
        if (rem >= 2)      { asm volatile("cp.async.wait_group 2;\n"); }
        else if (rem == 1) { asm volatile("cp.async.wait_group 1;\n"); }
        else               { asm volatile("cp.async.wait_group 0;\n"); }
        __syncthreads();
        if (g + 3 < G) issue(g + 3);

        int t = g >> kiLog, k = g & kiMask;
        int bm = tileBM(t);
        if (k == 0) {
            #pragma unroll
            for (int i = 0; i < 2; i++)
                #pragma unroll
                for (int j = 0; j < 8; j++)
                    #pragma unroll
                    for (int q = 0; q < 4; q++) acc[i][j][q] = 0.0f;
        }
        computeStage(g & 3);
        if (pfx2 != nullptr && bm >= splitM && k <= 1)
            snapshot((k == 0) ? pfx2 : pfx1, bm);
        if (k == kiMask) epilogue(bm);
    }
}

// ---------------- FA-style window attention: 1 block/window, warp-per-head ----------------
#define AQP 136
#define VTP 72
#define ATTN_SMEM (2 * 64 * AQP * 2 + NHn * 32 * VTP * 2)

__global__ __launch_bounds__(128) void attn_kernel(
    const bf16* __restrict__ QKVf,
    const bf16* __restrict__ QKV1,
    const bf16* __restrict__ QKV2,
    const float* __restrict__ CB,
    bf16* __restrict__ Of,
    bf16* __restrict__ O1,
    bf16* __restrict__ O2) {
    extern __shared__ bf16 ash[];
    bf16* sq  = ash;
    bf16* sk  = sq + 64 * AQP;
    bf16* svt = sk + 64 * AQP;

    int win = blockIdx.x;
    const bf16* QKV; bf16* O; int lw;
    if (win < NWIN_TOTAL)                  { QKV = QKVf; O = Of; lw = win; }
    else if (win < NWIN_TOTAL + NWIN_HALF) { QKV = QKV1; O = O1; lw = win - NWIN_TOTAL; }
    else                                   { QKV = QKV2; O = O2; lw = win - NWIN_TOTAL - NWIN_HALF; }
    const int mi = lw & 63;

    const int tid = threadIdx.x;
    const int wid = tid >> 5, lane = tid & 31;
    const int g = lane >> 2, t4 = lane & 3;
    const int h = wid;
    const int qcol = h * HDd;

    const bf16* base = QKV + (size_t)lw * Nn * 384;
    for (int idx = tid; idx < Nn * 16; idx += 128) {
        int n = idx >> 4, c8 = (idx & 15) << 3;
        *(uint4*)&sq[n * AQP + c8] = *(const uint4*)(base + n * 384 + c8);
        *(uint4*)&sk[n * AQP + c8] = *(const uint4*)(base + n * 384 + 128 + c8);
    }
    {
        const bf16* vb = base + 256 + qcol + lane;
        bf16* dst = svt + (h * 32 + lane) * VTP;
        #pragma unroll 4
        for (int m = 0; m < 64; m++)
            dst[m] = (m < Nn) ? vb[(size_t)m * 384] : __float2bfloat16(0.0f);
    }
    __syncthreads();

    const float* cb = CB + ((size_t)mi * NHn + h) * (Nn * Nn);

    uint32_t kf[2][4][4];
    #pragma unroll
    for (int ks = 0; ks < 2; ks++)
        #pragma unroll
        for (int nt2 = 0; nt2 < 4; nt2++)
            ldsm_x4(kf[ks][nt2], &sk[(nt2 * 16 + (lane & 7) + ((lane >> 4) << 3)) * AQP
                                      + qcol + ks * 16 + (((lane >> 3) & 1) << 3)]);
    uint32_t vf[4][2][4];
    #pragma unroll
    for (int kt = 0; kt < 4; kt++)
        #pragma unroll
        for (int nv = 0; nv < 2; nv++)
            ldsm_x4(vf[kt][nv], &svt[(h * 32 + nv * 16 + (lane & 7) + ((lane >> 4) << 3)) * VTP
                                      + kt * 16 + (((lane >> 3) & 1) << 3)]);

    #pragma unroll
    for (int mt = 0; mt < 4; mt++) {
        uint32_t qa[2][4];
        #pragma unroll
        for (int ks = 0; ks < 2; ks++)
            ldsm_x4(qa[ks], &sq[(mt * 16 + (lane & 15)) * AQP + qcol + ks * 16 + ((lane >> 4) << 3)]);

        float acc[7][4];
        #pragma unroll
        for (int nt = 0; nt < 7; nt++)
            #pragma unroll
            for (int q = 0; q < 4; q++) acc[nt][q] = 0.0f;
        #pragma unroll
        for (int ks = 0; ks < 2; ks++)
            #pragma unroll
            for (int nt = 0; nt < 7; nt++)
                mma_bf16(acc[nt], qa[ks], kf[ks][nt >> 1][(nt & 1) * 2], kf[ks][nt >> 1][(nt & 1) * 2 + 1]);

        const int r0 = mt * 16 + g, r1 = r0 + 8;
        #pragma unroll
        for (int nt = 0; nt < 7; nt++) {
            int c0 = nt * 8 + t4 * 2;
            acc[nt][0] = (c0 < Nn)     ? ((r0 < Nn) ? acc[nt][0] * SCALE + __ldg(&cb[r0 * Nn + c0])     : 0.0f) : -1e30f;
            acc[nt][1] = (c0 + 1 < Nn) ? ((r0 < Nn) ? acc[nt][1] * SCALE + __ldg(&cb[r0 * Nn + c0 + 1]) : 0.0f) : -1e30f;
            acc[nt][2] = (c0 < Nn)     ? ((r1 < Nn) ? acc[nt][2] * SCALE + __ldg(&cb[r1 * Nn + c0])     : 0.0f) : -1e30f;
            acc[nt][3] = (c0 + 1 < Nn) ? ((r1 < Nn) ? acc[nt][3] * SCALE + __ldg(&cb[r1 * Nn + c0 + 1]) : 0.0f) : -1e30f;
        }

        float mx0 = -1e30f, mx1 = -1e30f;
        #pragma unroll
        for (int nt = 0; nt < 7; nt++) {
            mx0 = fmaxf(mx0, fmaxf(acc[nt][0], acc[nt][1]));
            mx1 = fmaxf(mx1, fmaxf(acc[nt][2], acc[nt][3]));
        }
        mx0 = fmaxf(mx0, __shfl_xor_sync(0xffffffffu, mx0, 1));
        mx0 = fmaxf(mx0, __shfl_xor_sync(0xffffffffu, mx0, 2));
        mx1 = fmaxf(mx1, __shfl_xor_sync(0xffffffffu, mx1, 1));
        mx1 = fmaxf(mx1, __shfl_xor_sync(0xffffffffu, mx1, 2));
        float s0 = 0.0f, s1 = 0.0f;
        #pragma unroll
        for (int nt = 0; nt < 7; nt++) {
            acc[nt][0] = __expf(acc[nt][0] - mx0); s0 += acc[nt][0];
            acc[nt][1] = __expf(acc[nt][1] - mx0); s0 += acc[nt][1];
            acc[nt][2] = __expf(acc[nt][2] - mx1); s1 += acc[nt][2];
            acc[nt][3] = __expf(acc[nt][3] - mx1); s1 += acc[nt][3];
        }
        s0 += __shfl_xor_sync(0xffffffffu, s0, 1);
        s0 += __shfl_xor_sync(0xffffffffu, s0, 2);
        s1 += __shfl_xor_sync(0xffffffffu, s1, 1);
        s1 += __shfl_xor_sync(0xffffffffu, s1, 2);
        float rs0 = 1.0f / s0, rs1 = 1.0f / s1;

        uint32_t pf[4][4];
        #pragma unroll
        for (int kt = 0; kt < 4; kt++) {
            int n0 = 2 * kt, n1 = 2 * kt + 1;
            pf[kt][0] = packbf(acc[n0][0] * rs0, acc[n0][1] * rs0);
            pf[kt][1] = packbf(acc[n0][2] * rs1, acc[n0][3] * rs1);
            if (n1 < 7) {
                pf[kt][2] = packbf(acc[n1][0] * rs0, acc[n1][1] * rs0);
                pf[kt][3] = packbf(acc[n1][2] * rs1, acc[n1][3] * rs1);
            } else { pf[kt][2] = 0u; pf[kt][3] = 0u; }
        }

        float oacc[4][4];
        #pragma unroll
        for (int nt = 0; nt < 4; nt++)
            #pragma unroll
            for (int q = 0; q < 4; q++) oacc[nt][q] = 0.0f;
        #pragma unroll
        for (int kt = 0; kt < 4; kt++)
            #pragma unroll
            for (int nt = 0; nt < 4; nt++)
                mma_bf16(oacc[nt], pf[kt], vf[kt][nt >> 1][(nt & 1) * 2], vf[kt][nt >> 1][(nt & 1) * 2 + 1]);

        #pragma unroll
        for (int nt = 0; nt < 4; nt++) {
            int c = nt * 8 + t4 * 2;
            if (r0 < Nn)
                *(bf162*)(O + ((size_t)(lw * Nn + r0)) * Cdim + qcol + c)
                    = __floats2bfloat162_rn(oacc[nt][0], oacc[nt][1]);
            if (r1 < Nn)
                *(bf162*)(O + ((size_t)(lw * Nn + r1)) * Cdim + qcol + c)
                    = __floats2bfloat162_rn(oacc[nt][2], oacc[nt][3]);
        }
    }
}

// ---------------- host helpers ----------------
static inline void launch_gemm(const bf16* A, int lda, const bf16* B, int ldb,
                               const float* bias, void* C, int ldc,
                               int M, int N, int K,
                               const float* gwP, int ai, int aMode, int splitM,
                               int gelu, int outMode,
                               bf16* pfx2, bf16* pfx1, int pfxLd,
                               const float* xres, int rowOffset) {
    int nbn = (N + BN - 1) / BN;
    int nT = M / BM;
    int gy = 296 / nbn;
    if (gy > nT) gy = nT;
    if (gy < 1) gy = 1;
    dim3 grid(nbn, gy);
    bgemm<<<grid, 256, GEMM_SMEM>>>(A, lda, B, ldb, bias, C, ldc, M, N, K,
                                    gwP, ai, aMode, splitM, gelu, outMode,
                                    pfx2, pfx1, pfxLd, xres, rowOffset);
}

extern "C" void kernel_launch(void* const* d_in, const int* in_sizes, int n_in,
                              void* d_out, int out_size) {
    const float* x     = (const float*)d_in[0];
    const float* gw    = (const float*)d_in[1];
    const float* n1w   = (const float*)d_in[2];
    const float* n1b   = (const float*)d_in[3];
    const float* qkvw  = (const float*)d_in[4];
    const float* qkvb  = (const float*)d_in[5];
    const float* rbt   = (const float*)d_in[6];
    const float* projw = (const float*)d_in[7];
    const float* projb = (const float*)d_in[8];
    const float* amask = (const float*)d_in[9];
    const float* n2w   = (const float*)d_in[10];
    const float* n2b   = (const float*)d_in[11];
    const float* f1w   = (const float*)d_in[12];
    const float* f1b   = (const float*)d_in[13];
    const float* f2w   = (const float*)d_in[14];
    const float* f2b   = (const float*)d_in[15];
    const int*   relIdx= (const int*)d_in[16];
    float* out = (float*)d_out;

    cudaFuncSetAttribute(bgemm, cudaFuncAttributeMaxDynamicSharedMemorySize, GEMM_SMEM);
    cudaFuncSetAttribute(attn_kernel, cudaFuncAttributeMaxDynamicSharedMemorySize, ATTN_SMEM);

    bf16 *XW, *QKVf, *QKV1, *QKV2, *O, *Oh1, *Oh2, *XN, *Hb, *H1, *H2, *Wb;
    float *CB;
    cudaGetSymbolAddress((void**)&XW,   g_XW);
    cudaGetSymbolAddress((void**)&QKVf, g_QKVf);
    cudaGetSymbolAddress((void**)&QKV1, g_QKV1);
    cudaGetSymbolAddress((void**)&QKV2, g_QKV2);
    cudaGetSymbolAddress((void**)&O,    g_O);
    cudaGetSymbolAddress((void**)&Oh1,  g_Oh1);
    cudaGetSymbolAddress((void**)&Oh2,  g_Oh2);
    cudaGetSymbolAddress((void**)&XN,   g_XN);
    cudaGetSymbolAddress((void**)&Hb,   g_H);
    cudaGetSymbolAddress((void**)&H1,   g_H1);
    cudaGetSymbolAddress((void**)&H2,   g_H2);
    cudaGetSymbolAddress((void**)&CB,   g_CB);
    cudaGetSymbolAddress((void**)&Wb,   g_Wb);

    const bf16* qkvwB = Wb;
    const bf16* projwB = Wb + 49152;
    const bf16* f1wB = Wb + 65536;
    const bf16* f2wB = Wb + 131072;

    const int Mh = TOK_HALF;
    const int Mf = TOK_TOTAL;

    // prep: weight cast + bias table + LN1/partition
    prep_kernel<<<PREP_W + PREP_B + PREP_LN, 256>>>(
        qkvw, projw, f1w, f2w, Wb, rbt, relIdx, amask, CB, x, n1w, n1b, XW);

    // QKV merged: full (K=128) + prefix K=64 -> QKV1, K=32 -> QKV2
    launch_gemm(XW, Cdim, qkvwB, Cdim, qkvb, QKVf, 384, Mf, 384, 128,
                nullptr, 0, 0, Mh, 0, 0, QKV2, QKV1, 384, nullptr, 0);

    // attention: all variants, 1 block/window
    attn_kernel<<<NWIN_TOTAL + 2 * NWIN_HALF, 128, ATTN_SMEM>>>(
        QKVf, QKV1, QKV2, CB, O, Oh1, Oh2);

    // proj: out = x + alpha*v (permuted); variants RMW permuted
    launch_gemm(O, Cdim, projwB, Cdim, projb, out, Cdim, Mf, 128, 128,
                gw, 0, 2, Mh, 0, 1, nullptr, nullptr, 0, x, 0);
    launch_gemm(Oh1, Cdim, projwB, Cdim, projb, out, Cdim, Mh, 64, 128,
                gw, 1, 1, 0, 0, 2, nullptr, nullptr, 0, nullptr, Mh);
    launch_gemm(Oh2, Cdim, projwB, Cdim, projb, out, Cdim, Mh, 32, 128,
                gw, 2, 1, 0, 0, 2, nullptr, nullptr, 0, nullptr, Mh);

    // LN2 (out already holds residual)
    ln2_kernel<<<TOK_TOTAL / 8, 256>>>(out, n2w, n2b, XN);

    // ---- MLP, chunked so H stays L2-resident ----
    // half1: 2 chunks of MCH rows (no snapshots)
    for (int c = 0; c < 2; c++) {
        size_t off = (size_t)c * MCH;
        launch_gemm(XN + off * Cdim, Cdim, f1wB, Cdim, f1b, Hb, HID,
                    MCH, HID, 128, nullptr, 0, 0, 0, 1, 0,
                    nullptr, nullptr, 0, nullptr, 0);
        launch_gemm(Hb, HID, f2wB, HID, f2b, out + off * Cdim, Cdim,
                    MCH, 128, 512, nullptr, 0, 0, 0, 0, 3,
                    nullptr, nullptr, 0, nullptr, 0);
    }
    // half2: 2 chunks of MCH rows, with gelu'd K-prefix snapshots -> H1, H2
    for (int c = 0; c < 2; c++) {
        size_t off = (size_t)Mh + (size_t)c * MCH;
        launch_gemm(XN + off * Cdim, Cdim, f1wB, Cdim, f1b, Hb, HID,
                    MCH, HID, 128, nullptr, 0, 0, 0, 1, 0,
                    H2, H1, HID, nullptr, 0);
        launch_gemm(Hb, HID, f2wB, HID, f2b, out + off * Cdim, Cdim,
                    MCH, 128, 512, gw, 0, 1, 0, 0, 3,
                    nullptr, nullptr, 0, nullptr, 0);
        launch_gemm(H1, HID, f2wB, HID, f2b, out + off * Cdim, Cdim,
                    MCH, 64, 512, gw, 1, 1, 0, 0, 3,
                    nullptr, nullptr, 0, nullptr, 0);
        launch_gemm(H2, HID, f2wB, HID, f2b, out + off * Cdim, Cdim,
                    MCH, 32, 512, gw, 2, 1, 0, 0, 3,
                    nullptr, nullptr, 0, nullptr, 0);
    }
}

// round 15
// speedup vs baseline: 1.1555x; 1.1555x over previous
#include <cuda_runtime.h>
#include <cuda_bf16.h>
#include <cstdint>
#include <cstddef>
#include <math.h>

// ---------------- problem constants ----------------
#define Bimg 64
#define Hdim 56
#define Wdim 56
#define WS 7
#define SHIFT 3
#define Cdim 128
#define NHn 4
#define HDd 32
#define Nn 49
#define NWn 64
#define HID 512
#define SCALE 0.17677669529663688f

#define NWIN_TOTAL (Bimg * NWn)          // 4096
#define NWIN_HALF  (NWIN_TOTAL / 2)      // 2048
#define TOK_TOTAL  (NWIN_TOTAL * Nn)     // 200704
#define TOK_HALF   (NWIN_HALF * Nn)      // 100352

typedef __nv_bfloat16 bf16;
typedef __nv_bfloat162 bf162;

// ---------------- scratch (device globals) ----------------
__device__ bf16  g_XW  [(size_t)TOK_TOTAL * Cdim];
__device__ bf16  g_QKVf[(size_t)TOK_TOTAL * 384];
__device__ bf16  g_QKV1[(size_t)TOK_HALF  * 384];
__device__ bf16  g_QKV2[(size_t)TOK_HALF  * 384];
__device__ bf16  g_O   [(size_t)TOK_TOTAL * Cdim];
__device__ bf16  g_Oh1 [(size_t)TOK_HALF  * Cdim];
__device__ bf16  g_Oh2 [(size_t)TOK_HALF  * Cdim];
__device__ bf16  g_XN  [(size_t)TOK_TOTAL * Cdim];
__device__ float g_CB  [(size_t)NWn * NHn * Nn * Nn];
__device__ bf16  g_Wb  [196608];   // bf16 weights: qkvw|projw|f1w|f2w

// ---------------- fused prep: weights->bf16, bias+mask, LN1+roll+partition ----------------
#define PREP_W 192
#define PREP_B 256
#define PREP_LN (TOK_TOTAL / 8)
__global__ __launch_bounds__(256) void prep_kernel(
    const float* __restrict__ qkvw, const float* __restrict__ projw,
    const float* __restrict__ f1w, const float* __restrict__ f2w,
    bf16* __restrict__ Wb,
    const float* __restrict__ rbt, const int* __restrict__ relIdx,
    const float* __restrict__ mask, float* __restrict__ CB,
    const float* __restrict__ x, const float* __restrict__ n1w,
    const float* __restrict__ n1b, bf16* __restrict__ XW) {
    int bid = blockIdx.x;
    if (bid < PREP_W) {
        int i = (bid * 256 + threadIdx.x) * 4;
        const float* src; int off;
        if (i < 49152)       { src = qkvw;  off = i; }
        else if (i < 65536)  { src = projw; off = i - 49152; }
        else if (i < 131072) { src = f1w;   off = i - 65536; }
        else                 { src = f2w;   off = i - 131072; }
        float4 v = *(const float4*)(src + off);
        *(bf162*)(Wb + i)     = __floats2bfloat162_rn(v.x, v.y);
        *(bf162*)(Wb + i + 2) = __floats2bfloat162_rn(v.z, v.w);
        return;
    }
    if (bid < PREP_W + PREP_B) {
        int b = bid - PREP_W;
        int mi = b >> 2, h = b & 3;
        float* dst = CB + ((size_t)mi * NHn + h) * (Nn * Nn);
        const float* msk = mask + (size_t)mi * (Nn * Nn);
        for (int idx = threadIdx.x; idx < Nn * Nn; idx += 256)
            dst[idx] = __ldg(&rbt[relIdx[idx] * NHn + h]) + msk[idx];
        return;
    }
    int t = (bid - PREP_W - PREP_B) * 8 + (threadIdx.x >> 5);
    int lane = threadIdx.x & 31;
    int win = t / Nn, n = t - win * Nn;
    int bi = win >> 6, wi = win & 63;
    int hs = ((wi >> 3) * WS + n / WS + SHIFT) % Hdim;
    int ws = ((wi & 7) * WS + n % WS + SHIFT) % Wdim;
    const float* xp = x + ((size_t)bi * (Hdim * Wdim) + hs * Wdim + ws) * Cdim;
    float4 v = *(const float4*)(xp + lane * 4);
    float s  = v.x + v.y + v.z + v.w;
    float s2 = v.x * v.x + v.y * v.y + v.z * v.z + v.w * v.w;
    #pragma unroll
    for (int o = 16; o > 0; o >>= 1) {
        s  += __shfl_xor_sync(0xffffffffu, s, o);
        s2 += __shfl_xor_sync(0xffffffffu, s2, o);
    }
    float mu  = s * (1.0f / Cdim);
    float var = s2 * (1.0f / Cdim) - mu * mu;
    float inv = rsqrtf(var + 1e-5f);
    float4 wv = *(const float4*)(n1w + lane * 4);
    float4 bv = *(const float4*)(n1b + lane * 4);
    bf16* dst = XW + (size_t)t * Cdim + lane * 4;
    *(bf162*)(dst)     = __floats2bfloat162_rn((v.x - mu) * inv * wv.x + bv.x,
                                               (v.y - mu) * inv * wv.y + bv.y);
    *(bf162*)(dst + 2) = __floats2bfloat162_rn((v.z - mu) * inv * wv.z + bv.z,
                                               (v.w - mu) * inv * wv.w + bv.w);
}

// ---------------- LN2 (image layout, out holds residual already) ----------------
__global__ __launch_bounds__(256) void ln2_kernel(const float* __restrict__ out,
                                                  const float* __restrict__ w,
                                                  const float* __restrict__ b,
                                                  bf16* __restrict__ XN) {
    int t = blockIdx.x * 8 + (threadIdx.x >> 5);
    int lane = threadIdx.x & 31;
    float4 v = *(const float4*)(out + (size_t)t * Cdim + lane * 4);
    float s  = v.x + v.y + v.z + v.w;
    float s2 = v.x * v.x + v.y * v.y + v.z * v.z + v.w * v.w;
    #pragma unroll
    for (int o = 16; o > 0; o >>= 1) {
        s  += __shfl_xor_sync(0xffffffffu, s, o);
        s2 += __shfl_xor_sync(0xffffffffu, s2, o);
    }
    float mu  = s * (1.0f / Cdim);
    float var = s2 * (1.0f / Cdim) - mu * mu;
    float inv = rsqrtf(var + 1e-5f);
    float4 wv = *(const float4*)(w + lane * 4);
    float4 bv = *(const float4*)(b + lane * 4);
    bf16* dst = XN + (size_t)t * Cdim + lane * 4;
    *(bf162*)(dst)     = __floats2bfloat162_rn((v.x - mu) * inv * wv.x + bv.x,
                                               (v.y - mu) * inv * wv.y + bv.y);
    *(bf162*)(dst + 2) = __floats2bfloat162_rn((v.z - mu) * inv * wv.z + bv.z,
                                               (v.w - mu) * inv * wv.w + bv.w);
}

// ---------------- mma / ldmatrix helpers ----------------
__device__ __forceinline__ void mma_bf16(float* c, const uint32_t* a, uint32_t b0, uint32_t b1) {
    asm volatile("mma.sync.aligned.m16n8k16.row.col.f32.bf16.bf16.f32 "
        "{%0,%1,%2,%3}, {%4,%5,%6,%7}, {%8,%9}, {%0,%1,%2,%3};\n"
        : "+f"(c[0]), "+f"(c[1]), "+f"(c[2]), "+f"(c[3])
        : "r"(a[0]), "r"(a[1]), "r"(a[2]), "r"(a[3]), "r"(b0), "r"(b1));
}
__device__ __forceinline__ void ldsm_x4(uint32_t* r, const bf16* p) {
    uint32_t addr = (uint32_t)__cvta_generic_to_shared(p);
    asm volatile("ldmatrix.sync.aligned.m8n8.x4.shared.b16 {%0,%1,%2,%3}, [%4];\n"
        : "=r"(r[0]), "=r"(r[1]), "=r"(r[2]), "=r"(r[3]) : "r"(addr));
}
__device__ __forceinline__ void cpa16(uint32_t dst, const void* src, bool pred) {
    int sz = pred ? 16 : 0;
    asm volatile("cp.async.cg.shared.global [%0], [%1], 16, %2;\n"
                 :: "r"(dst), "l"(src), "r"(sz));
}
__device__ __forceinline__ uint32_t packbf(float a, float b) {
    bf162 t = __floats2bfloat162_rn(a, b);
    return *(uint32_t*)&t;
}
__device__ __forceinline__ float gelu_f(float v) {
    return 0.5f * v * (1.0f + erff(v * 0.70710678118654752f));
}
__device__ __forceinline__ size_t perm_pos(int r) {
    int win = r / Nn, n = r - win * Nn;
    int bi = win >> 6, wi = win & 63;
    int hs = ((wi >> 3) * WS + n / WS + SHIFT) % Hdim;
    int ws = ((wi & 7) * WS + n % WS + SHIFT) % Wdim;
    return ((size_t)bi * (Hdim * Wdim) + hs * Wdim + ws) * Cdim;
}

// ---------------- persistent BF16 GEMM (QKV + proj) ----------------
// outMode: 0 = bf16 store (ldc), 1 = perm + x add (fp32), 2 = perm RMW (fp32)
#define BM 128
#define BN 128
#define BK 32
#define GST 40
#define STG_E (BM * GST)
#define NSTG 4
#define GEMM_SMEM (NSTG * 2 * STG_E * 2)

__global__ __launch_bounds__(256, 2) void bgemm(
    const bf16* __restrict__ A, int lda,
    const bf16* __restrict__ B, int ldb,
    const float* __restrict__ bias,
    void* __restrict__ Cv, int ldc,
    int M, int N, int K,
    const float* __restrict__ gwPtr, int alphaIdx, int alphaMode, int splitM,
    int outMode,
    bf16* __restrict__ pfx2, bf16* __restrict__ pfx1, int pfxLd,
    const float* __restrict__ xres, int rowOffset) {
    extern __shared__ bf16 smem[];
    bf16* As = smem;
    bf16* Bs = smem + NSTG * STG_E;

    const int tid = threadIdx.x;
    const int bn = blockIdx.x * BN;
    const int wid = tid >> 5, lane = tid & 31;
    const int wm = (wid & 3) * 32;
    const int wn = (wid >> 2) * 64;
    const int g4 = lane >> 2, t4 = lane & 3;

    const int lrow = tid >> 2;
    const int lc = (tid & 3) * 8;
    const bf16* Bg = B + (size_t)(bn + lrow) * ldb + lc;
    const bool bval0 = (bn + lrow) < N;
    const bool bval1 = (bn + lrow + 64) < N;

    const int KI = K / BK;      // 4
    const int nT = M / BM;
    const int GYm = gridDim.y;
    const int myT = (nT - (int)blockIdx.y + GYm - 1) / GYm;
    if (myT <= 0) return;
    const int G = myT * KI;

    float acc[2][8][4];
    auto tileBM = [&](int t) { return ((int)blockIdx.y + t * GYm) * BM; };

    auto issue = [&](int g) {
        int t = g >> 2, k = g & 3;
        int bm = tileBM(t);
        int st = g & 3;
        uint32_t a0 = (uint32_t)__cvta_generic_to_shared(&As[st * STG_E + lrow * GST + lc]);
        const bf16* Agp = A + (size_t)(bm + lrow) * lda + k * BK + lc;
        cpa16(a0, Agp, true);
        cpa16(a0 + 64 * GST * 2, Agp + (size_t)64 * lda, true);
        if (g < 4) {
            uint32_t b0 = (uint32_t)__cvta_generic_to_shared(&Bs[st * STG_E + lrow * GST + lc]);
            cpa16(b0, Bg + k * BK, bval0);
            cpa16(b0 + 64 * GST * 2, Bg + k * BK + (size_t)64 * ldb, bval1);
        }
        asm volatile("cp.async.commit_group;\n");
    };

    auto computeStage = [&](int st) {
        const bf16* Ab = &As[st * STG_E];
        const bf16* Bb = &Bs[st * STG_E];
        #pragma unroll
        for (int ks = 0; ks < 2; ks++) {
            const int kb = ks * 16;
            uint32_t af[2][4];
            #pragma unroll
            for (int mt = 0; mt < 2; mt++)
                ldsm_x4(af[mt], &Ab[(wm + mt * 16 + (lane & 15)) * GST + kb + ((lane >> 4) << 3)]);
            uint32_t bfm[8][2];
            #pragma unroll
            for (int nt2 = 0; nt2 < 4; nt2++) {
                uint32_t r4[4];
                ldsm_x4(r4, &Bb[(wn + nt2 * 16 + (lane & 7) + ((lane >> 4) << 3)) * GST
                                 + kb + (((lane >> 3) & 1) << 3)]);
                bfm[nt2 * 2][0] = r4[0]; bfm[nt2 * 2][1] = r4[1];
                bfm[nt2 * 2 + 1][0] = r4[2]; bfm[nt2 * 2 + 1][1] = r4[3];
            }
            #pragma unroll
            for (int nt = 0; nt < 8; nt++) {
                mma_bf16(acc[0][nt], af[0], bfm[nt][0], bfm[nt][1]);
                mma_bf16(acc[1][nt], af[1], bfm[nt][0], bfm[nt][1]);
            }
        }
    };

    auto snapshot = [&](bf16* __restrict__ P, int bm) {
        #pragma unroll
        for (int nt = 0; nt < 8; nt++) {
            int c0 = bn + wn + nt * 8 + t4 * 2;
            if (c0 >= N) continue;
            float bv0 = bias ? bias[c0] : 0.0f;
            float bv1 = bias ? bias[c0 + 1] : 0.0f;
            #pragma unroll
            for (int mt = 0; mt < 2; mt++)
                #pragma unroll
                for (int half = 0; half < 2; half++) {
                    int r = bm + wm + mt * 16 + g4 + half * 8;
                    *(bf162*)(P + (size_t)(r - splitM) * pfxLd + c0)
                        = __floats2bfloat162_rn(acc[mt][nt][half * 2 + 0] + bv0,
                                                acc[mt][nt][half * 2 + 1] + bv1);
                }
        }
    };

    auto epilogue = [&](int bm) {
        float alpha = 1.0f;
        if (alphaMode == 1) alpha = __ldg(&gwPtr[alphaIdx]);
        else if (alphaMode == 2 && bm >= splitM) alpha = __ldg(&gwPtr[0]);
        size_t pos[2][2];
        if (outMode != 0) {
            #pragma unroll
            for (int mt = 0; mt < 2; mt++)
                #pragma unroll
                for (int half = 0; half < 2; half++)
                    pos[mt][half] = perm_pos(rowOffset + bm + wm + mt * 16 + g4 + half * 8);
        }
        #pragma unroll
        for (int nt = 0; nt < 8; nt++) {
            int c0 = bn + wn + nt * 8 + t4 * 2;
            if (c0 >= N) continue;
            float bv0 = bias ? bias[c0] : 0.0f;
            float bv1 = bias ? bias[c0 + 1] : 0.0f;
            #pragma unroll
            for (int mt = 0; mt < 2; mt++) {
                #pragma unroll
                for (int half = 0; half < 2; half++) {
                    int r = bm + wm + mt * 16 + g4 + half * 8;
                    float v0 = (acc[mt][nt][half * 2 + 0] + bv0) * alpha;
                    float v1 = (acc[mt][nt][half * 2 + 1] + bv1) * alpha;
                    if (outMode == 0) {
                        size_t off = (size_t)r * ldc + c0;
                        *(bf162*)((bf16*)Cv + off) = __floats2bfloat162_rn(v0, v1);
                    } else {
                        size_t off = pos[mt][half] + c0;
                        float* Cf = (float*)Cv;
                        if (outMode == 1) {
                            float2 xv = *(const float2*)(xres + off);
                            v0 += xv.x; v1 += xv.y;
                        } else {
                            float2 old = *(const float2*)(Cf + off);
                            v0 += old.x; v1 += old.y;
                        }
                        *(float2*)(Cf + off) = make_float2(v0, v1);
                    }
                }
            }
        }
    };

    issue(0); issue(1); issue(2);

    #pragma unroll 1
    for (int g = 0; g < G; g++) {
        int rem = G - 1 - g;
        if (rem >= 2)      { asm volatile("cp.async.wait_group 2;\n"); }
        else if (rem == 1) { asm volatile("cp.async.wait_group 1;\n"); }
        else               { asm volatile("cp.async.wait_group 0;\n"); }
        __syncthreads();
        if (g + 3 < G) issue(g + 3);

        int t = g >> 2, k = g & 3;
        int bm = tileBM(t);
        if (k == 0) {
            #pragma unroll
            for (int i = 0; i < 2; i++)
                #pragma unroll
                for (int j = 0; j < 8; j++)
                    #pragma unroll
                    for (int q = 0; q < 4; q++) acc[i][j][q] = 0.0f;
        }
        computeStage(g & 3);
        if (pfx2 != nullptr && bm >= splitM && k <= 1)
            snapshot((k == 0) ? pfx2 : pfx1, bm);
        if (k == 3) epilogue(bm);
    }
}

// ---------------- FA-style window attention: 1 block/window, warp-per-head ----------------
#define AQP 136
#define VTP 72
#define ATTN_SMEM (2 * 64 * AQP * 2 + NHn * 32 * VTP * 2)

__global__ __launch_bounds__(128) void attn_kernel(
    const bf16* __restrict__ QKVf,
    const bf16* __restrict__ QKV1,
    const bf16* __restrict__ QKV2,
    const float* __restrict__ CB,
    bf16* __restrict__ Of,
    bf16* __restrict__ O1,
    bf16* __restrict__ O2) {
    extern __shared__ bf16 ash[];
    bf16* sq  = ash;
    bf16* sk  = sq + 64 * AQP;
    bf16* svt = sk + 64 * AQP;

    int win = blockIdx.x;
    const bf16* QKV; bf16* O; int lw;
    if (win < NWIN_TOTAL)                  { QKV = QKVf; O = Of; lw = win; }
    else if (win < NWIN_TOTAL + NWIN_HALF) { QKV = QKV1; O = O1; lw = win - NWIN_TOTAL; }
    else                                   { QKV = QKV2; O = O2; lw = win - NWIN_TOTAL - NWIN_HALF; }
    const int mi = lw & 63;

    const int tid = threadIdx.x;
    const int wid = tid >> 5, lane = tid & 31;
    const int g = lane >> 2, t4 = lane & 3;
    const int h = wid;
    const int qcol = h * HDd;

    const bf16* base = QKV + (size_t)lw * Nn * 384;
    for (int idx = tid; idx < Nn * 16; idx += 128) {
        int n = idx >> 4, c8 = (idx & 15) << 3;
        *(uint4*)&sq[n * AQP + c8] = *(const uint4*)(base + n * 384 + c8);
        *(uint4*)&sk[n * AQP + c8] = *(const uint4*)(base + n * 384 + 128 + c8);
    }
    {
        const bf16* vb = base + 256 + qcol + lane;
        bf16* dst = svt + (h * 32 + lane) * VTP;
        #pragma unroll 4
        for (int m = 0; m < 64; m++)
            dst[m] = (m < Nn) ? vb[(size_t)m * 384] : __float2bfloat16(0.0f);
    }
    __syncthreads();

    const float* cb = CB + ((size_t)mi * NHn + h) * (Nn * Nn);

    uint32_t kf[2][4][4];
    #pragma unroll
    for (int ks = 0; ks < 2; ks++)
        #pragma unroll
        for (int nt2 = 0; nt2 < 4; nt2++)
            ldsm_x4(kf[ks][nt2], &sk[(nt2 * 16 + (lane & 7) + ((lane >> 4) << 3)) * AQP
                                      + qcol + ks * 16 + (((lane >> 3) & 1) << 3)]);
    uint32_t vf[4][2][4];
    #pragma unroll
    for (int kt = 0; kt < 4; kt++)
        #pragma unroll
        for (int nv = 0; nv < 2; nv++)
            ldsm_x4(vf[kt][nv], &svt[(h * 32 + nv * 16 + (lane & 7) + ((lane >> 4) << 3)) * VTP
                                      + kt * 16 + (((lane >> 3) & 1) << 3)]);

    #pragma unroll
    for (int mt = 0; mt < 4; mt++) {
        uint32_t qa[2][4];
        #pragma unroll
        for (int ks = 0; ks < 2; ks++)
            ldsm_x4(qa[ks], &sq[(mt * 16 + (lane & 15)) * AQP + qcol + ks * 16 + ((lane >> 4) << 3)]);

        float acc[7][4];
        #pragma unroll
        for (int nt = 0; nt < 7; nt++)
            #pragma unroll
            for (int q = 0; q < 4; q++) acc[nt][q] = 0.0f;
        #pragma unroll
        for (int ks = 0; ks < 2; ks++)
            #pragma unroll
            for (int nt = 0; nt < 7; nt++)
                mma_bf16(acc[nt], qa[ks], kf[ks][nt >> 1][(nt & 1) * 2], kf[ks][nt >> 1][(nt & 1) * 2 + 1]);

        const int r0 = mt * 16 + g, r1 = r0 + 8;
        #pragma unroll
        for (int nt = 0; nt < 7; nt++) {
            int c0 = nt * 8 + t4 * 2;
            acc[nt][0] = (c0 < Nn)     ? ((r0 < Nn) ? acc[nt][0] * SCALE + __ldg(&cb[r0 * Nn + c0])     : 0.0f) : -1e30f;
            acc[nt][1] = (c0 + 1 < Nn) ? ((r0 < Nn) ? acc[nt][1] * SCALE + __ldg(&cb[r0 * Nn + c0 + 1]) : 0.0f) : -1e30f;
            acc[nt][2] = (c0 < Nn)     ? ((r1 < Nn) ? acc[nt][2] * SCALE + __ldg(&cb[r1 * Nn + c0])     : 0.0f) : -1e30f;
            acc[nt][3] = (c0 + 1 < Nn) ? ((r1 < Nn) ? acc[nt][3] * SCALE + __ldg(&cb[r1 * Nn + c0 + 1]) : 0.0f) : -1e30f;
        }

        float mx0 = -1e30f, mx1 = -1e30f;
        #pragma unroll
        for (int nt = 0; nt < 7; nt++) {
            mx0 = fmaxf(mx0, fmaxf(acc[nt][0], acc[nt][1]));
            mx1 = fmaxf(mx1, fmaxf(acc[nt][2], acc[nt][3]));
        }
        mx0 = fmaxf(mx0, __shfl_xor_sync(0xffffffffu, mx0, 1));
        mx0 = fmaxf(mx0, __shfl_xor_sync(0xffffffffu, mx0, 2));
        mx1 = fmaxf(mx1, __shfl_xor_sync(0xffffffffu, mx1, 1));
        mx1 = fmaxf(mx1, __shfl_xor_sync(0xffffffffu, mx1, 2));
        float s0 = 0.0f, s1 = 0.0f;
        #pragma unroll
        for (int nt = 0; nt < 7; nt++) {
            acc[nt][0] = __expf(acc[nt][0] - mx0); s0 += acc[nt][0];
            acc[nt][1] = __expf(acc[nt][1] - mx0); s0 += acc[nt][1];
            acc[nt][2] = __expf(acc[nt][2] - mx1); s1 += acc[nt][2];
            acc[nt][3] = __expf(acc[nt][3] - mx1); s1 += acc[nt][3];
        }
        s0 += __shfl_xor_sync(0xffffffffu, s0, 1);
        s0 += __shfl_xor_sync(0xffffffffu, s0, 2);
        s1 += __shfl_xor_sync(0xffffffffu, s1, 1);
        s1 += __shfl_xor_sync(0xffffffffu, s1, 2);
        float rs0 = 1.0f / s0, rs1 = 1.0f / s1;

        uint32_t pf[4][4];
        #pragma unroll
        for (int kt = 0; kt < 4; kt++) {
            int n0 = 2 * kt, n1 = 2 * kt + 1;
            pf[kt][0] = packbf(acc[n0][0] * rs0, acc[n0][1] * rs0);
            pf[kt][1] = packbf(acc[n0][2] * rs1, acc[n0][3] * rs1);
            if (n1 < 7) {
                pf[kt][2] = packbf(acc[n1][0] * rs0, acc[n1][1] * rs0);
                pf[kt][3] = packbf(acc[n1][2] * rs1, acc[n1][3] * rs1);
            } else { pf[kt][2] = 0u; pf[kt][3] = 0u; }
        }

        float oacc[4][4];
        #pragma unroll
        for (int nt = 0; nt < 4; nt++)
            #pragma unroll
            for (int q = 0; q < 4; q++) oacc[nt][q] = 0.0f;
        #pragma unroll
        for (int kt = 0; kt < 4; kt++)
            #pragma unroll
            for (int nt = 0; nt < 4; nt++)
                mma_bf16(oacc[nt], pf[kt], vf[kt][nt >> 1][(nt & 1) * 2], vf[kt][nt >> 1][(nt & 1) * 2 + 1]);

        #pragma unroll
        for (int nt = 0; nt < 4; nt++) {
            int c = nt * 8 + t4 * 2;
            if (r0 < Nn)
                *(bf162*)(O + ((size_t)(lw * Nn + r0)) * Cdim + qcol + c)
                    = __floats2bfloat162_rn(oacc[nt][0], oacc[nt][1]);
            if (r1 < Nn)
                *(bf162*)(O + ((size_t)(lw * Nn + r1)) * Cdim + qcol + c)
                    = __floats2bfloat162_rn(oacc[nt][2], oacc[nt][3]);
        }
    }
}

// ---------------- fused MLP, 512 threads (16 warps, 4x4 warp grid) ----------------
#define SXP 136
#define FMLP_SMEM (6 * 128 * SXP * 2)   // 208896 B

__global__ __launch_bounds__(512, 1) void fmlp(
    const bf16* __restrict__ XN,
    const bf16* __restrict__ W1,          // (512,128) bf16
    const float* __restrict__ f1b,
    const bf16* __restrict__ W2,          // (128,512) bf16
    const float* __restrict__ f2b,
    const float* __restrict__ gw,
    float* __restrict__ out, int splitM) {
    extern __shared__ bf16 sm[];
    bf16* sX  = sm;
    bf16* sW1 = sX + 128 * SXP;
    bf16* sW2 = sW1 + 2 * 128 * SXP;
    bf16* sH  = sW2 + 2 * 128 * SXP;

    const int b = blockIdx.x;
    const int bm = (b & 1) ? (splitM + (b >> 1) * 128) : ((b >> 1) * 128);
    const bool half2 = bm >= splitM;
    const int tid = threadIdx.x;
    const int wid = tid >> 5, lane = tid & 31;
    const int wm = (wid & 3) * 32;       // 4 M positions
    const int wn = (wid >> 2) * 32;      // 4 N positions
    const int g4 = lane >> 2, t4 = lane & 3;
    const int lrow = tid >> 2;           // 0..127
    const int lcb = (tid & 3) * 32;      // 0,32,64,96

    {   // XN tile (resident): 128 x 128
        const bf16* src = XN + (size_t)(bm + lrow) * Cdim + lcb;
        uint32_t d = (uint32_t)__cvta_generic_to_shared(&sX[lrow * SXP + lcb]);
        #pragma unroll
        for (int i = 0; i < 4; i++) cpa16(d + i * 16, src + i * 8, true);
        asm volatile("cp.async.commit_group;\n");
    }
    auto issueW = [&](int c) {
        int buf = c & 1;
        const bf16* s1 = W1 + (size_t)(c * 128 + lrow) * Cdim + lcb;
        uint32_t d1 = (uint32_t)__cvta_generic_to_shared(&sW1[buf * 128 * SXP + lrow * SXP + lcb]);
        const bf16* s2 = W2 + (size_t)lrow * HID + c * 128 + lcb;
        uint32_t d2 = (uint32_t)__cvta_generic_to_shared(&sW2[buf * 128 * SXP + lrow * SXP + lcb]);
        #pragma unroll
        for (int i = 0; i < 4; i++) {
            cpa16(d1 + i * 16, s1 + i * 8, true);
            cpa16(d2 + i * 16, s2 + i * 8, true);
        }
        asm volatile("cp.async.commit_group;\n");
    };
    issueW(0); issueW(1);

    const float a0 = half2 ? __ldg(&gw[0]) : 1.0f;
    const float a1 = __ldg(&gw[1]);
    const float a2 = __ldg(&gw[2]);

    float accO[2][4][4];
    #pragma unroll
    for (int i = 0; i < 2; i++)
        #pragma unroll
        for (int j = 0; j < 4; j++)
            #pragma unroll
            for (int q = 0; q < 4; q++) accO[i][j][q] = 0.0f;

    float accH[2][4][4];

    #pragma unroll 1
    for (int c = 0; c < 4; c++) {
        if (c < 3) { asm volatile("cp.async.wait_group 1;\n"); }
        else       { asm volatile("cp.async.wait_group 0;\n"); }
        __syncthreads();
        const bf16* w1b = &sW1[(c & 1) * 128 * SXP];
        const bf16* w2b = &sW2[(c & 1) * 128 * SXP];

        #pragma unroll
        for (int i = 0; i < 2; i++)
            #pragma unroll
            for (int j = 0; j < 4; j++)
                #pragma unroll
                for (int q = 0; q < 4; q++) accH[i][j][q] = 0.0f;

        auto s1k = [&](int ki) {
            #pragma unroll
            for (int kh = 0; kh < 2; kh++) {
                int kb = ki * 32 + kh * 16;
                uint32_t af[2][4];
                #pragma unroll
                for (int mt = 0; mt < 2; mt++)
                    ldsm_x4(af[mt], &sX[(wm + mt * 16 + (lane & 15)) * SXP + kb + ((lane >> 4) << 3)]);
                #pragma unroll
                for (int nt2 = 0; nt2 < 2; nt2++) {
                    uint32_t r4[4];
                    ldsm_x4(r4, &w1b[(wn + nt2 * 16 + (lane & 7) + ((lane >> 4) << 3)) * SXP
                                      + kb + (((lane >> 3) & 1) << 3)]);
                    mma_bf16(accH[0][nt2 * 2],     af[0], r4[0], r4[1]);
                    mma_bf16(accH[0][nt2 * 2 + 1], af[0], r4[2], r4[3]);
                    mma_bf16(accH[1][nt2 * 2],     af[1], r4[0], r4[1]);
                    mma_bf16(accH[1][nt2 * 2 + 1], af[1], r4[2], r4[3]);
                }
            }
        };
        auto writeH = [&](float scale) {
            #pragma unroll
            for (int nt = 0; nt < 4; nt++) {
                int cc = wn + nt * 8 + t4 * 2;
                float b0 = __ldg(&f1b[c * 128 + cc]);
                float b1 = __ldg(&f1b[c * 128 + cc + 1]);
                #pragma unroll
                for (int mt = 0; mt < 2; mt++)
                    #pragma unroll
                    for (int half = 0; half < 2; half++) {
                        int r = wm + mt * 16 + g4 + half * 8;
                        float v0 = gelu_f(accH[mt][nt][half * 2 + 0] + b0) * scale;
                        float v1 = gelu_f(accH[mt][nt][half * 2 + 1] + b1) * scale;
                        *(bf162*)(sH + r * SXP + cc) = __floats2bfloat162_rn(v0, v1);
                    }
            }
        };
        auto s2pass = [&](int maxcol) {
            #pragma unroll
            for (int kb = 0; kb < 128; kb += 16) {
                uint32_t af[2][4];
                #pragma unroll
                for (int mt = 0; mt < 2; mt++)
                    ldsm_x4(af[mt], &sH[(wm + mt * 16 + (lane & 15)) * SXP + kb + ((lane >> 4) << 3)]);
                #pragma unroll
                for (int nt2 = 0; nt2 < 2; nt2++) {
                    if (wn + nt2 * 16 >= maxcol) continue;
                    uint32_t r4[4];
                    ldsm_x4(r4, &w2b[(wn + nt2 * 16 + (lane & 7) + ((lane >> 4) << 3)) * SXP
                                      + kb + (((lane >> 3) & 1) << 3)]);
                    mma_bf16(accO[0][nt2 * 2],     af[0], r4[0], r4[1]);
                    mma_bf16(accO[0][nt2 * 2 + 1], af[0], r4[2], r4[3]);
                    mma_bf16(accO[1][nt2 * 2],     af[1], r4[0], r4[1]);
                    mma_bf16(accO[1][nt2 * 2 + 1], af[1], r4[2], r4[3]);
                }
            }
        };

        if (half2) {
            s1k(0); writeH(a2); __syncthreads(); s2pass(32);  __syncthreads();
            s1k(1); writeH(a1); __syncthreads(); s2pass(64);  __syncthreads();
            s1k(2); s1k(3);
            writeH(a0); __syncthreads(); s2pass(128); __syncthreads();
        } else {
            s1k(0); s1k(1); s1k(2); s1k(3);
            writeH(1.0f); __syncthreads(); s2pass(128); __syncthreads();
        }
        if (c + 2 < 4) issueW(c + 2);
    }

    // epilogue: out += accO + coef(col)*f2b
    #pragma unroll
    for (int nt = 0; nt < 4; nt++) {
        int cc = wn + nt * 8 + t4 * 2;
        float coef = half2 ? ((cc < 32) ? (a0 + a1 + a2) : (cc < 64) ? (a0 + a1) : a0) : 1.0f;
        float b0 = __ldg(&f2b[cc]) * coef;
        float b1 = __ldg(&f2b[cc + 1]) * coef;
        #pragma unroll
        for (int mt = 0; mt < 2; mt++)
            #pragma unroll
            for (int half = 0; half < 2; half++) {
                int r = bm + wm + mt * 16 + g4 + half * 8;
                size_t off = (size_t)r * Cdim + cc;
                float2 old = *(const float2*)(out + off);
                old.x += accO[mt][nt][half * 2 + 0] + b0;
                old.y += accO[mt][nt][half * 2 + 1] + b1;
                *(float2*)(out + off) = old;
            }
    }
}

// ---------------- host helpers ----------------
static inline void launch_gemm(const bf16* A, int lda, const bf16* B, int ldb,
                               const float* bias, void* C, int ldc,
                               int M, int N, int K,
                               const float* gwP, int ai, int aMode, int splitM,
                               int outMode,
                               bf16* pfx2, bf16* pfx1, int pfxLd,
                               const float* xres, int rowOffset) {
    int nbn = (N + BN - 1) / BN;
    int nT = M / BM;
    int gy = 296 / nbn;
    if (gy > nT) gy = nT;
    if (gy < 1) gy = 1;
    dim3 grid(nbn, gy);
    bgemm<<<grid, 256, GEMM_SMEM>>>(A, lda, B, ldb, bias, C, ldc, M, N, K,
                                    gwP, ai, aMode, splitM, outMode,
                                    pfx2, pfx1, pfxLd, xres, rowOffset);
}

extern "C" void kernel_launch(void* const* d_in, const int* in_sizes, int n_in,
                              void* d_out, int out_size) {
    const float* x     = (const float*)d_in[0];
    const float* gw    = (const float*)d_in[1];
    const float* n1w   = (const float*)d_in[2];
    const float* n1b   = (const float*)d_in[3];
    const float* qkvw  = (const float*)d_in[4];
    const float* qkvb  = (const float*)d_in[5];
    const float* rbt   = (const float*)d_in[6];
    const float* projw = (const float*)d_in[7];
    const float* projb = (const float*)d_in[8];
    const float* amask = (const float*)d_in[9];
    const float* n2w   = (const float*)d_in[10];
    const float* n2b   = (const float*)d_in[11];
    const float* f1w   = (const float*)d_in[12];
    const float* f1b   = (const float*)d_in[13];
    const float* f2w   = (const float*)d_in[14];
    const float* f2b   = (const float*)d_in[15];
    const int*   relIdx= (const int*)d_in[16];
    float* out = (float*)d_out;

    cudaFuncSetAttribute(bgemm, cudaFuncAttributeMaxDynamicSharedMemorySize, GEMM_SMEM);
    cudaFuncSetAttribute(attn_kernel, cudaFuncAttributeMaxDynamicSharedMemorySize, ATTN_SMEM);
    cudaFuncSetAttribute(fmlp, cudaFuncAttributeMaxDynamicSharedMemorySize, FMLP_SMEM);

    bf16 *XW, *QKVf, *QKV1, *QKV2, *O, *Oh1, *Oh2, *XN, *Wb;
    float *CB;
    cudaGetSymbolAddress((void**)&XW,   g_XW);
    cudaGetSymbolAddress((void**)&QKVf, g_QKVf);
    cudaGetSymbolAddress((void**)&QKV1, g_QKV1);
    cudaGetSymbolAddress((void**)&QKV2, g_QKV2);
    cudaGetSymbolAddress((void**)&O,    g_O);
    cudaGetSymbolAddress((void**)&Oh1,  g_Oh1);
    cudaGetSymbolAddress((void**)&Oh2,  g_Oh2);
    cudaGetSymbolAddress((void**)&XN,   g_XN);
    cudaGetSymbolAddress((void**)&CB,   g_CB);
    cudaGetSymbolAddress((void**)&Wb,   g_Wb);

    const bf16* qkvwB = Wb;
    const bf16* projwB = Wb + 49152;
    const bf16* f1wB = Wb + 65536;
    const bf16* f2wB = Wb + 131072;

    const int Mh = TOK_HALF;
    const int Mf = TOK_TOTAL;

    // prep: weight cast + bias table + LN1/partition
    prep_kernel<<<PREP_W + PREP_B + PREP_LN, 256>>>(
        qkvw, projw, f1w, f2w, Wb, rbt, relIdx, amask, CB, x, n1w, n1b, XW);

    // QKV merged: full (K=128) + prefix K=64 -> QKV1, K=32 -> QKV2
    launch_gemm(XW, Cdim, qkvwB, Cdim, qkvb, QKVf, 384, Mf, 384, 128,
                nullptr, 0, 0, Mh, 0, QKV2, QKV1, 384, nullptr, 0);

    // attention: all variants, 1 block/window
    attn_kernel<<<NWIN_TOTAL + 2 * NWIN_HALF, 128, ATTN_SMEM>>>(
        QKVf, QKV1, QKV2, CB, O, Oh1, Oh2);

    // proj: out = x + alpha*v (permuted); variants RMW permuted
    launch_gemm(O, Cdim, projwB, Cdim, projb, out, Cdim, Mf, 128, 128,
                gw, 0, 2, Mh, 1, nullptr, nullptr, 0, x, 0);
    launch_gemm(Oh1, Cdim, projwB, Cdim, projb, out, Cdim, Mh, 64, 128,
                gw, 1, 1, 0, 2, nullptr, nullptr, 0, nullptr, Mh);
    launch_gemm(Oh2, Cdim, projwB, Cdim, projb, out, Cdim, Mh, 32, 128,
                gw, 2, 1, 0, 2, nullptr, nullptr, 0, nullptr, Mh);

    // LN2 (out already holds residual)
    ln2_kernel<<<TOK_TOTAL / 8, 256>>>(out, n2w, n2b, XN);

    // fused MLP (512 threads): out += all variants
    fmlp<<<Mf / 128, 512, FMLP_SMEM>>>(XN, f1wB, f1b, f2wB, f2b, gw, out, Mh);
}